// round 17
// baseline (speedup 1.0000x reference)
#include <cuda_runtime.h>
#include <cstdint>

#define BQ   2
#define SEQ  2048
#define DIM  1024
#define NH   16
#define DKH  64
#define MTOT (BQ*SEQ)            // 4096
#define NELEM (BQ*SEQ*DIM)       // 8388608
#define WELEM (DIM*DIM)          // 1048576

// ---------------------------------------------------------------------------
// Scratch (__device__ globals; allocation-free rule)
// ---------------------------------------------------------------------------
__device__ float g_Q  [NELEM];   // Q proj, tf32-rounded
__device__ float g_K  [NELEM];   // K proj, tf32-rounded
__device__ float g_Vt [BQ*NH*DKH*SEQ];  // V proj, rounded, [b,h,d,key]
__device__ float g_AO [NELEM];   // attention output, tf32-rounded
__device__ float g_rw0[WELEM];   // tf32-rounded weights
__device__ float g_rw1[WELEM];
__device__ float g_rw2[WELEM];
__device__ float g_rw3[WELEM];

// ---------------------------------------------------------------------------
// Helpers
// ---------------------------------------------------------------------------
__device__ __forceinline__ uint32_t smem_u32(const void* p) {
    uint32_t a;
    asm("{ .reg .u64 t; cvta.to.shared.u64 t, %1; cvt.u32.u64 %0, t; }"
        : "=r"(a) : "l"(p));
    return a;
}

__device__ __forceinline__ uint32_t tf32_bits(float x) {
    uint32_t u;
    asm("cvt.rna.tf32.f32 %0, %1;" : "=r"(u) : "f"(x));
    return u;
}
__device__ __forceinline__ float tf32_rnf(float x) {
    return __uint_as_float(tf32_bits(x));
}

#define LDSM_X4(r, addr)                                                        \
    asm volatile("ldmatrix.sync.aligned.m8n8.x4.shared.b16 {%0,%1,%2,%3}, [%4];"\
                 : "=r"((r)[0]), "=r"((r)[1]), "=r"((r)[2]), "=r"((r)[3])       \
                 : "r"(addr))

#define MMA_TF32(d, a, b)                                                       \
    asm volatile("mma.sync.aligned.m16n8k8.row.col.f32.tf32.tf32.f32 "          \
                 "{%0,%1,%2,%3}, {%4,%5,%6,%7}, {%8,%9}, {%0,%1,%2,%3};"        \
                 : "+f"((d)[0]), "+f"((d)[1]), "+f"((d)[2]), "+f"((d)[3])       \
                 : "r"((a)[0]), "r"((a)[1]), "r"((a)[2]), "r"((a)[3]),          \
                   "r"((b)[0]), "r"((b)[1]))

#define CP16(dst, src)                                                          \
    asm volatile("cp.async.cg.shared.global [%0], [%1], 16;"                    \
                 :: "r"(dst), "l"(src) : "memory")

// ---------------------------------------------------------------------------
// Weight pre-rounding, all 4 weights in one launch (grid.y = weight idx)
// ---------------------------------------------------------------------------
__global__ void round_w(const float* __restrict__ w0, const float* __restrict__ w1,
                        const float* __restrict__ w2, const float* __restrict__ w3)
{
    const float* src;
    float* dst;
    switch (blockIdx.y) {
        case 0:  src = w0; dst = g_rw0; break;
        case 1:  src = w1; dst = g_rw1; break;
        case 2:  src = w2; dst = g_rw2; break;
        default: src = w3; dst = g_rw3; break;
    }
    int i = blockIdx.x * blockDim.x + threadIdx.x;
    float4 v = ((const float4*)src)[i];
    v.x = tf32_rnf(v.x); v.y = tf32_rnf(v.y);
    v.z = tf32_rnf(v.z); v.w = tf32_rnf(v.w);
    ((float4*)dst)[i] = v;
}

// ---------------------------------------------------------------------------
// tf32 mma.sync GEMM:  C = A[4096,1024] @ W[1024,1024]^T + bias
// CTA 128x64 (8 warps x 32x32 warp tile), BK=32, 3-stage cp.async,
// 2 CTAs/SM (regs <= 128 via launch_bounds, smem 82944 B).
// Epilogues: IDX0 -> g_Q rounded; IDX1 -> g_K rounded;
//            IDX2 -> g_Vt rounded transposed; IDX3 -> Cout plain (A=g_AO).
// ---------------------------------------------------------------------------
#define GASZ   (128 * 36 * 4)             // 18432 B A tile
#define GBSZ   (64 * 36 * 4)              //  9216 B B tile
#define GSTAGE (GASZ + GBSZ)              // 27648 B
#define GNSTAGE 3
#define GEMM_SMEM (GNSTAGE * GSTAGE)      // 82944 B

template <int IDX>
__global__ void __launch_bounds__(256, 2) gemm_mma(const float* __restrict__ Ain,
                                                   const float* __restrict__ bias,
                                                   float* __restrict__ Cout)
{
    extern __shared__ __align__(16) char smem[];
    const uint32_t sb = smem_u32(smem);
    const int tid  = threadIdx.x;
    const int wid  = tid >> 5;
    const int lane = tid & 31;

    const float* __restrict__ A = (IDX == 3) ? g_AO : Ain;
    const float* __restrict__ W;
    if      (IDX == 0) W = g_rw0;
    else if (IDX == 1) W = g_rw1;
    else if (IDX == 2) W = g_rw2;
    else               W = g_rw3;

    const int col0 = blockIdx.x * 64;
    const int row0 = blockIdx.y * 128;

    auto load_chunk = [&](int c) {
        const uint32_t st = sb + (c % GNSTAGE) * GSTAGE;
        const int k0 = c * 32;
#pragma unroll
        for (int i = 0; i < 4; ++i) {              // A: 128 rows x 8 16B-chunks
            int f   = tid + (i << 8);
            int r   = f >> 3;
            int c16 = f & 7;
            CP16(st + (uint32_t)(r * 144 + c16 * 16),
                 A + (size_t)(row0 + r) * DIM + k0 + c16 * 4);
        }
#pragma unroll
        for (int i = 0; i < 2; ++i) {              // B: 64 rows x 8 16B-chunks
            int f   = tid + (i << 8);
            int r   = f >> 3;
            int c16 = f & 7;
            CP16(st + GASZ + (uint32_t)(r * 144 + c16 * 16),
                 W + (size_t)(col0 + r) * DIM + k0 + c16 * 4);
        }
        asm volatile("cp.async.commit_group;" ::: "memory");
    };

    load_chunk(0); load_chunk(1); load_chunk(2);

    const int wm = (wid & 3) * 32;                 // 4 M-warps
    const int wn = (wid >> 2) * 32;                // 2 N-warps
    const int arow = (lane & 7) + ((lane >> 3) & 1) * 8;
    const int asel = lane >> 4;
    const int brow = lane & 7;
    const int bsel = lane >> 3;

    float d[2][4][4];
#pragma unroll
    for (int mt = 0; mt < 2; ++mt)
#pragma unroll
        for (int nt = 0; nt < 4; ++nt)
#pragma unroll
            for (int j = 0; j < 4; ++j) d[mt][nt][j] = 0.f;

    for (int c = 0; c < 32; ++c) {
        asm volatile("cp.async.wait_group 2;" ::: "memory");
        __syncthreads();

        const uint32_t As = sb + (c % GNSTAGE) * GSTAGE;
        const uint32_t Bs = As + GASZ;

        uint32_t b[4][4];
#pragma unroll
        for (int ks = 0; ks < 4; ++ks) {
            uint32_t a[2][4];
#pragma unroll
            for (int mt = 0; mt < 2; ++mt) {
                LDSM_X4(a[mt], As + (uint32_t)((wm + mt * 16 + arow) * 144
                                               + (ks * 2 + asel) * 16));
                if (IDX != 3) {
#pragma unroll
                    for (int j = 0; j < 4; ++j)
                        a[mt][j] = tf32_bits(__uint_as_float(a[mt][j]));
                }
            }
            if ((ks & 1) == 0) {
#pragma unroll
                for (int nt = 0; nt < 4; ++nt)
                    LDSM_X4(b[nt], Bs + (uint32_t)((wn + nt * 8 + brow) * 144
                                                   + (ks * 8 + bsel * 4) * 4));
            }
#pragma unroll
            for (int mt = 0; mt < 2; ++mt)
#pragma unroll
                for (int nt = 0; nt < 4; ++nt)
                    MMA_TF32(d[mt][nt], a[mt], &b[nt][(ks & 1) * 2]);
        }
        __syncthreads();
        if (c + 3 < 32) load_chunk(c + 3);
    }

    const int rr = row0 + wm + (lane >> 2);
    const int cc = col0 + wn + (lane & 3) * 2;
#pragma unroll
    for (int mt = 0; mt < 2; ++mt) {
#pragma unroll
        for (int nt = 0; nt < 4; ++nt) {
            int cn = cc + nt * 8;
            float bx = bias[cn], by = bias[cn + 1];
            int r1 = rr + mt * 16;
            float v00 = d[mt][nt][0] + bx, v01 = d[mt][nt][1] + by;
            float v10 = d[mt][nt][2] + bx, v11 = d[mt][nt][3] + by;
            if (IDX == 0 || IDX == 1) {
                float* G = (IDX == 0) ? g_Q : g_K;
                float2 o0 = { tf32_rnf(v00), tf32_rnf(v01) };
                float2 o1 = { tf32_rnf(v10), tf32_rnf(v11) };
                *(float2*)(G + (size_t)r1 * DIM + cn)       = o0;
                *(float2*)(G + (size_t)(r1 + 8) * DIM + cn) = o1;
            } else if (IDX == 2) {
                int hh = cn >> 6, dd = cn & 63;
#pragma unroll
                for (int mm = 0; mm < 2; ++mm) {
                    int tok = r1 + mm * 8;
                    int bb  = tok >> 11, key = tok & 2047;
                    size_t rowb = ((size_t)(bb * NH + hh) * DKH);
                    float x0 = mm ? v10 : v00, x1 = mm ? v11 : v01;
                    g_Vt[(rowb + dd)     * SEQ + key] = tf32_rnf(x0);
                    g_Vt[(rowb + dd + 1) * SEQ + key] = tf32_rnf(x1);
                }
            } else {
                float2 o0 = { v00, v01 }, o1 = { v10, v11 };
                *(float2*)(Cout + (size_t)r1 * DIM + cn)       = o0;
                *(float2*)(Cout + (size_t)(r1 + 8) * DIM + cn) = o1;
            }
        }
    }
}

// ---------------------------------------------------------------------------
// Causal flash attention (unchanged from round 15 — passing).
// ---------------------------------------------------------------------------
#define FS   68
#define FA_SMEM ((128 + 64 + 64) * FS * 4)   // 69632 B

__global__ void __launch_bounds__(256, 2) flash_mma()
{
    extern __shared__ float sm[];
    const uint32_t sQ = smem_u32(sm);
    const uint32_t sK = sQ + 128 * FS * 4;
    const uint32_t sV = sK + 64 * FS * 4;

    const int tid  = threadIdx.x;
    const int lane = tid & 31;
    const int wid  = tid >> 5;
    const int qti  = (int)gridDim.x - 1 - (int)blockIdx.x;   // heavy tiles first
    const int h    = blockIdx.y;
    const int b    = blockIdx.z;
    const int qbase = qti * 128;
    const size_t hbase  = (size_t)b * SEQ * DIM + (size_t)h * DKH;
    const size_t vtbase = (size_t)(b * NH + h) * DKH * SEQ;

    const int nkt = 2 * qti + 2;

    auto load_K = [&](int kt) {
        const int ktb = kt * 64;
#pragma unroll
        for (int i = 0; i < 4; ++i) {
            int idx = tid + (i << 8);
            int r   = idx >> 4;
            int c16 = idx & 15;
            CP16(sK + (uint32_t)((r * FS + c16 * 4) * 4),
                 g_K + hbase + (size_t)(ktb + r) * DIM + c16 * 4);
        }
        asm volatile("cp.async.commit_group;" ::: "memory");
    };
    auto load_V = [&](int kt) {
        const int ktb = kt * 64;
#pragma unroll
        for (int i = 0; i < 4; ++i) {
            int idx = tid + (i << 8);
            int r   = idx >> 4;
            int c16 = idx & 15;
            CP16(sV + (uint32_t)((r * FS + c16 * 4) * 4),
                 g_Vt + vtbase + (size_t)r * SEQ + ktb + c16 * 4);
        }
        asm volatile("cp.async.commit_group;" ::: "memory");
    };

    // prologue: Q (uncommitted) + K0 -> one group; V0 -> second group
#pragma unroll
    for (int i = 0; i < 8; ++i) {
        int idx = tid + (i << 8);
        int r   = idx >> 4;
        int c16 = idx & 15;
        CP16(sQ + (uint32_t)((r * FS + c16 * 4) * 4),
             g_Q + hbase + (size_t)(qbase + r) * DIM + c16 * 4);
    }
    load_K(0);      // commits Q + K0 together
    load_V(0);

    const int qr0   = wid * 16;
    const int arow  = (lane & 7) + ((lane >> 3) & 1) * 8;
    const int asel  = lane >> 4;
    const int brow  = lane & 7;
    const int bsel  = lane >> 3;
    const int qrow  = lane >> 2;
    const int t4    = lane & 3;
    const int cpair = t4 * 2;
    const int shsrc0 = t4 >> 1;
    const int shsrc1 = (t4 >> 1) + 2;
    const bool odd   = (t4 & 1);
    const uint32_t vks_off = (uint32_t)((lane & 7) * FS * 4 + (lane >> 3) * 16);

    float oacc[8][4];
#pragma unroll
    for (int nt = 0; nt < 8; ++nt)
#pragma unroll
        for (int j = 0; j < 4; ++j) oacc[nt][j] = 0.f;
    float m0 = -3.0e38f, m1 = -3.0e38f, l0 = 0.f, l1 = 0.f;

    for (int kt = 0; kt < nkt; ++kt) {
        const int ktb = kt * 64;
        asm volatile("cp.async.wait_group 1;" ::: "memory");   // K_kt ready
        __syncthreads();

        // ---- S = Q K^T ----
        float sacc[8][4];
#pragma unroll
        for (int nt = 0; nt < 8; ++nt)
#pragma unroll
            for (int j = 0; j < 4; ++j) sacc[nt][j] = 0.f;

        uint32_t kb[8][4];
#pragma unroll
        for (int ks = 0; ks < 8; ++ks) {
            uint32_t qa[4];
            LDSM_X4(qa, sQ + (uint32_t)((qr0 + arow) * FS * 4 + (ks * 2 + asel) * 16));
            if ((ks & 1) == 0) {
#pragma unroll
                for (int nt = 0; nt < 8; ++nt)
                    LDSM_X4(kb[nt], sK + (uint32_t)((nt * 8 + brow) * FS * 4
                                                    + (ks * 8 + bsel * 4) * 4));
            }
#pragma unroll
            for (int nt = 0; nt < 8; ++nt)
                MMA_TF32(sacc[nt], qa, &kb[nt][(ks & 1) * 2]);
        }

        // ---- mask + scale ----
        const int qg0 = qbase + qr0 + qrow;
        const int qg1 = qg0 + 8;
        const bool domask = (kt >= 2 * qti);
#pragma unroll
        for (int nt = 0; nt < 8; ++nt) {
            int kg = ktb + nt * 8 + cpair;
            if (domask) {
                sacc[nt][0] = (kg     <= qg0) ? sacc[nt][0] * 0.125f : -3.0e38f;
                sacc[nt][1] = (kg + 1 <= qg0) ? sacc[nt][1] * 0.125f : -3.0e38f;
                sacc[nt][2] = (kg     <= qg1) ? sacc[nt][2] * 0.125f : -3.0e38f;
                sacc[nt][3] = (kg + 1 <= qg1) ? sacc[nt][3] * 0.125f : -3.0e38f;
            } else {
#pragma unroll
                for (int j = 0; j < 4; ++j) sacc[nt][j] *= 0.125f;
            }
        }

        // ---- online softmax ----
        float tm0 = -3.0e38f, tm1 = -3.0e38f;
#pragma unroll
        for (int nt = 0; nt < 8; ++nt) {
            tm0 = fmaxf(tm0, fmaxf(sacc[nt][0], sacc[nt][1]));
            tm1 = fmaxf(tm1, fmaxf(sacc[nt][2], sacc[nt][3]));
        }
        tm0 = fmaxf(tm0, __shfl_xor_sync(0xffffffffu, tm0, 1));
        tm0 = fmaxf(tm0, __shfl_xor_sync(0xffffffffu, tm0, 2));
        tm1 = fmaxf(tm1, __shfl_xor_sync(0xffffffffu, tm1, 1));
        tm1 = fmaxf(tm1, __shfl_xor_sync(0xffffffffu, tm1, 2));

        float nm0 = fmaxf(m0, tm0), nm1 = fmaxf(m1, tm1);
        float a0s = __expf(m0 - nm0), a1s = __expf(m1 - nm1);
        m0 = nm0; m1 = nm1;

        float ts0 = 0.f, ts1 = 0.f;
#pragma unroll
        for (int nt = 0; nt < 8; ++nt) {
            sacc[nt][0] = __expf(sacc[nt][0] - nm0);
            sacc[nt][1] = __expf(sacc[nt][1] - nm0);
            sacc[nt][2] = __expf(sacc[nt][2] - nm1);
            sacc[nt][3] = __expf(sacc[nt][3] - nm1);
            ts0 += sacc[nt][0] + sacc[nt][1];
            ts1 += sacc[nt][2] + sacc[nt][3];
        }
        ts0 += __shfl_xor_sync(0xffffffffu, ts0, 1);
        ts0 += __shfl_xor_sync(0xffffffffu, ts0, 2);
        ts1 += __shfl_xor_sync(0xffffffffu, ts1, 1);
        ts1 += __shfl_xor_sync(0xffffffffu, ts1, 2);
        l0 = l0 * a0s + ts0;
        l1 = l1 * a1s + ts1;
#pragma unroll
        for (int nt = 0; nt < 8; ++nt) {
            oacc[nt][0] *= a0s; oacc[nt][1] *= a0s;
            oacc[nt][2] *= a1s; oacc[nt][3] *= a1s;
        }

        // ---- convert P: C-frag -> A-frag via quad shuffles ----
        uint32_t pa[8][4];
#pragma unroll
        for (int nt = 0; nt < 8; ++nt) {
            float x0 = __shfl_sync(0xffffffffu, sacc[nt][0], shsrc0, 4);
            float x1 = __shfl_sync(0xffffffffu, sacc[nt][1], shsrc0, 4);
            float x2 = __shfl_sync(0xffffffffu, sacc[nt][2], shsrc0, 4);
            float x3 = __shfl_sync(0xffffffffu, sacc[nt][3], shsrc0, 4);
            float y0 = __shfl_sync(0xffffffffu, sacc[nt][0], shsrc1, 4);
            float y1 = __shfl_sync(0xffffffffu, sacc[nt][1], shsrc1, 4);
            float y2 = __shfl_sync(0xffffffffu, sacc[nt][2], shsrc1, 4);
            float y3 = __shfl_sync(0xffffffffu, sacc[nt][3], shsrc1, 4);
            pa[nt][0] = tf32_bits(odd ? x1 : x0);
            pa[nt][1] = tf32_bits(odd ? x3 : x2);
            pa[nt][2] = tf32_bits(odd ? y1 : y0);
            pa[nt][3] = tf32_bits(odd ? y3 : y2);
        }

        // ---- prefetch K(kt+1) ----
        __syncthreads();
        if (kt + 1 < nkt) {
            load_K(kt + 1);
            asm volatile("cp.async.wait_group 1;" ::: "memory");   // V_kt ready
        } else {
            asm volatile("cp.async.wait_group 0;" ::: "memory");
        }
        __syncthreads();

        // ---- O += P V ----
#pragma unroll
        for (int kp = 0; kp < 4; ++kp) {
#pragma unroll
            for (int nt = 0; nt < 8; ++nt) {
                uint32_t v4[4];
                LDSM_X4(v4, sV + vks_off + (uint32_t)(nt * 8 * FS * 4 + kp * 64));
                MMA_TF32(oacc[nt], pa[2 * kp],     v4 + 0);
                MMA_TF32(oacc[nt], pa[2 * kp + 1], v4 + 2);
            }
        }

        // ---- prefetch V(kt+1) ----
        __syncthreads();
        if (kt + 1 < nkt) load_V(kt + 1);
    }

    // ---- epilogue: normalize + tf32-round ----
    const float inv0 = 1.0f / l0, inv1 = 1.0f / l1;
    const int r0 = qbase + qr0 + qrow;
#pragma unroll
    for (int nt = 0; nt < 8; ++nt) {
        int col = nt * 8 + cpair;
        float2 o0 = { tf32_rnf(oacc[nt][0] * inv0), tf32_rnf(oacc[nt][1] * inv0) };
        float2 o1 = { tf32_rnf(oacc[nt][2] * inv1), tf32_rnf(oacc[nt][3] * inv1) };
        *(float2*)(g_AO + hbase + (size_t)r0 * DIM + col)       = o0;
        *(float2*)(g_AO + hbase + (size_t)(r0 + 8) * DIM + col) = o1;
    }
}

// ---------------------------------------------------------------------------
extern "C" void kernel_launch(void* const* d_in, const int* in_sizes, int n_in,
                              void* d_out, int out_size)
{
    (void)in_sizes; (void)n_in; (void)out_size;
    const float* q   = (const float*)d_in[0];
    const float* k   = (const float*)d_in[1];
    const float* v   = (const float*)d_in[2];
    // d_in[3] = mask (deterministic causal tril) — handled implicitly
    const float* w_q = (const float*)d_in[4];
    const float* b_q = (const float*)d_in[5];
    const float* w_k = (const float*)d_in[6];
    const float* b_k = (const float*)d_in[7];
    const float* w_v = (const float*)d_in[8];
    const float* b_v = (const float*)d_in[9];
    const float* w_o = (const float*)d_in[10];
    const float* b_o = (const float*)d_in[11];

    static bool attr_done = false;
    if (!attr_done) {
        cudaFuncSetAttribute(gemm_mma<0>, cudaFuncAttributeMaxDynamicSharedMemorySize, GEMM_SMEM);
        cudaFuncSetAttribute(gemm_mma<1>, cudaFuncAttributeMaxDynamicSharedMemorySize, GEMM_SMEM);
        cudaFuncSetAttribute(gemm_mma<2>, cudaFuncAttributeMaxDynamicSharedMemorySize, GEMM_SMEM);
        cudaFuncSetAttribute(gemm_mma<3>, cudaFuncAttributeMaxDynamicSharedMemorySize, GEMM_SMEM);
        cudaFuncSetAttribute(flash_mma,   cudaFuncAttributeMaxDynamicSharedMemorySize, FA_SMEM);
        attr_done = true;
    }

    dim3 gw(WELEM / 4 / 256, 4);
    round_w<<<gw, 256>>>(w_q, w_k, w_v, w_o);

    dim3 gg(DIM / 64, MTOT / 128);    // (16, 32) = 512 CTAs
    gemm_mma<0><<<gg, 256, GEMM_SMEM>>>(q, b_q, nullptr);
    gemm_mma<1><<<gg, 256, GEMM_SMEM>>>(k, b_k, nullptr);
    gemm_mma<2><<<gg, 256, GEMM_SMEM>>>(v, b_v, nullptr);

    dim3 ga(SEQ / 128, NH, BQ);       // (16, 16, 2)
    flash_mma<<<ga, 256, FA_SMEM>>>();

    gemm_mma<3><<<gg, 256, GEMM_SMEM>>>(nullptr, b_o, (float*)d_out);
}